// round 16
// baseline (speedup 1.0000x reference)
#include <cuda_runtime.h>
#include <math.h>
#include <stdint.h>

#define N_TOK   131072
#define D_DIM   192
#define K_CODE  128
#define GBLK    1024              // N_TOK / 128
#define SCALE_L 28.853900817779268f   // 20 / ln(2): Lc = cos*20*log2(e)

// ---------------- scratch (device globals; no runtime allocation) ------------
__device__ float g_Lc[(size_t)N_TOK * K_CODE];   // 67 MB: Lc[n][k]
__device__ float g_Rpart[GBLK * K_CODE];         // block partials, [block][k]
__device__ float g_rvec[K_CODE];                 // r1 then r2
__device__ float g_lr3[K_CODE];                  // log2(r3)
__device__ __align__(16) float g_memT[D_DIM * K_CODE];  // normalized bank, [d][k]
__device__ __align__(16) float g_hg[K_CODE * D_DIM];    // 0.5 * gated(mem_bank[k])
__device__ unsigned g_cnt[3];                    // last-block counters (reset by kprep)

// ---------------- small helpers ---------------------------------------------
__device__ __forceinline__ float ex2f(float x) {
    float y; asm("ex2.approx.f32 %0, %1;" : "=f"(y) : "f"(x)); return y;
}
__device__ __forceinline__ unsigned long long pk2(float x) {
    unsigned long long r; asm("mov.b64 %0, {%1, %1};" : "=l"(r) : "f"(x)); return r;
}
__device__ __forceinline__ float2 up2(unsigned long long v) {
    float2 r; asm("mov.b64 {%0, %1}, %2;" : "=f"(r.x), "=f"(r.y) : "l"(v)); return r;
}
__device__ __forceinline__ void fma2(unsigned long long& a, unsigned long long x,
                                     unsigned long long m) {
    asm("fma.rn.f32x2 %0, %1, %2, %0;" : "+l"(a) : "l"(x), "l"(m));
}
__device__ __forceinline__ void cpa16(uint32_t dst, const void* src) {
    asm volatile("cp.async.cg.shared.global [%0], [%1], 16;" :: "r"(dst), "l"(src));
}
__device__ __forceinline__ void cpa_commit() {
    asm volatile("cp.async.commit_group;");
}
__device__ __forceinline__ void cpa_wait0() {
    asm volatile("cp.async.wait_group 0;");
}
// streaming (evict-first) float4 load / store
__device__ __forceinline__ float4 ldcs4(const float* p) {
    float4 v;
    asm volatile("ld.global.cs.v4.f32 {%0,%1,%2,%3}, [%4];"
                 : "=f"(v.x), "=f"(v.y), "=f"(v.z), "=f"(v.w) : "l"(p));
    return v;
}
__device__ __forceinline__ void stcs4(float* p, float4 v) {
    asm volatile("st.global.cs.v4.f32 [%0], {%1,%2,%3,%4};"
                 :: "l"(p), "f"(v.x), "f"(v.y), "f"(v.z), "f"(v.w));
}
// L2 (bypass L1) scalar load for the tail reduce
__device__ __forceinline__ float ldcg(const float* p) {
    float v; asm volatile("ld.global.cg.f32 %0, [%1];" : "=f"(v) : "l"(p));
    return v;
}
// 16B-granular XOR swizzle along the token axis of an sX row (col in floats)
__device__ __forceinline__ int swzc(int c) { return c ^ (((c >> 5) & 1) << 2); }

// ---------------- fused tail reduce (bit-identical to old kreduce) ----------
// Thread t<128 owns code t: four 256-term ascending chains, combine
// ((q0+q1)+q2)+q3 — identical values/order to the kreduce kernel it replaces.
__device__ __forceinline__ void tail_reduce(int mode, int tid) {
    if (tid < 128) {
        float q[4];
        #pragma unroll
        for (int p = 0; p < 4; p++) {
            float s = 0.f;
            const float* ptr = g_Rpart + (size_t)(p * 256) * K_CODE + tid;
            #pragma unroll 32
            for (int i = 0; i < 256; i++) s += ldcg(ptr + (size_t)i * K_CODE);
            q[p] = s;
        }
        float tot = ((q[0] + q[1]) + q[2]) + q[3];
        if (mode == 0) g_rvec[tid] = 1.0f / tot;
        else           g_lr3[tid]  = -log2f(tot);
    }
}
// returns true in the last block to arrive (after its partials are visible)
__device__ __forceinline__ bool last_block(int which, int tid, unsigned grid) {
    __shared__ int sLast;
    __threadfence();
    __syncthreads();
    if (tid == 0) {
        unsigned old = atomicAdd(&g_cnt[which], 1u);
        sLast = (old == grid - 1u);
    }
    __syncthreads();
    if (sLast) __threadfence();
    return sLast != 0;
}

// ---------------- K0: per-code norm + transposed bank + GLU table (fused) ---
__global__ void kprep(const float* __restrict__ mem, const float* __restrict__ W,
                      const float* __restrict__ b) {
    __shared__ float a[D_DIM];
    __shared__ float s_scale;
    int k = blockIdx.x, j = threadIdx.x;
    if (k == 0 && j == 0) { g_cnt[0] = 0; g_cnt[1] = 0; g_cnt[2] = 0; }
    a[j] = mem[k * D_DIM + j];
    __syncthreads();
    if (j == 0) {
        float s = 0.f;
        #pragma unroll 8
        for (int d = 0; d < D_DIM; d++) s = fmaf(a[d], a[d], s);   // R2 bit order
        s_scale = 1.0f / sqrtf(fmaxf(s, 1e-12f));
    }
    __syncthreads();
    g_memT[j * K_CODE + k] = a[j] * s_scale;
    float av = b[j], ag = b[j + D_DIM];
    #pragma unroll 4
    for (int d = 0; d < D_DIM; d++) {
        float xd = a[d];
        av = fmaf(xd, W[d * 2 * D_DIM + j], av);
        ag = fmaf(xd, W[d * 2 * D_DIM + D_DIM + j], ag);
    }
    float sig = 1.0f / (1.0f + expf(-ag));
    g_hg[k * D_DIM + j] = 0.5f * av * sig;
}

// ---------------- K1: similarity GEMM — R10 core + fused r1 reduce ----------
__global__ __launch_bounds__(256, 2) void kgemm(const float* __restrict__ proj) {
    __shared__ __align__(16) float sX[2][16][132];   // [buf][dd][token(swz)+pad]
    __shared__ __align__(16) float sM[2][16][128];   // [buf][dd][code]
    __shared__ float sScale[128];
    __shared__ float sRed[16][128];

    int tid = threadIdx.x, lane = tid & 31, w = tid >> 5;
    int tx = (lane & 3) | ((w & 3) << 2);         // code group (4 distinct / warp)
    int ty = ((lane >> 2) & 7) | ((w >> 2) << 3); // token group (8 distinct / warp)
    int t0 = blockIdx.x << 7;
    int tokA = tid >> 2, q = tid & 3, tokB = tokA + 64;
    int cA = swzc(tokA), cB = swzc(tokB);

    uint32_t mb0 = (uint32_t)__cvta_generic_to_shared(&sM[0][0][0]);
    uint32_t mb1 = (uint32_t)__cvta_generic_to_shared(&sM[1][0][0]);
    int fA = tid, fB = tid + 256;

    unsigned long long acc[8][4];
    #pragma unroll
    for (int i = 0; i < 8; i++)
        #pragma unroll
        for (int j = 0; j < 4; j++) acc[i][j] = 0ULL;
    float nacc = 0.f;

    auto stageM = [&](int dc, int buf) {
        uint32_t mb = buf ? mb1 : mb0;
        cpa16(mb + (uint32_t)(fA * 16), g_memT + dc * 2048 + fA * 4);
        cpa16(mb + (uint32_t)(fB * 16), g_memT + dc * 2048 + fB * 4);
        cpa_commit();
    };

    stageM(0, 0);
    {
        float4 xA = ldcs4(proj + (size_t)(t0 + tokA) * D_DIM + q * 4);
        float4 xB = ldcs4(proj + (size_t)(t0 + tokB) * D_DIM + q * 4);
        sX[0][q * 4 + 0][cA] = xA.x; sX[0][q * 4 + 1][cA] = xA.y;
        sX[0][q * 4 + 2][cA] = xA.z; sX[0][q * 4 + 3][cA] = xA.w;
        sX[0][q * 4 + 0][cB] = xB.x; sX[0][q * 4 + 1][cB] = xB.y;
        sX[0][q * 4 + 2][cB] = xB.z; sX[0][q * 4 + 3][cB] = xB.w;
    }

    for (int dc = 0; dc < 12; dc++) {
        int cur = dc & 1, nxt = cur ^ 1;
        cpa_wait0();
        __syncthreads();

        float4 pxA, pxB;
        if (dc < 11) {
            stageM(dc + 1, nxt);
            pxA = ldcs4(proj + (size_t)(t0 + tokA) * D_DIM + (dc + 1) * 16 + q * 4);
            pxB = ldcs4(proj + (size_t)(t0 + tokB) * D_DIM + (dc + 1) * 16 + q * 4);
        }

        if (tid < 128) {
            int ct = swzc(tid);
            #pragma unroll
            for (int dd = 0; dd < 16; dd++) {
                float x = sX[cur][dd][ct];
                nacc = fmaf(x, x, nacc);
            }
        }
        #pragma unroll
        for (int dd = 0; dd < 16; dd++) {
            float4 xa = *(const float4*)&sX[cur][dd][swzc(ty * 8)];
            float4 xb = *(const float4*)&sX[cur][dd][swzc(ty * 8 + 4)];
            ulonglong2 m0 = ((const ulonglong2*)&sM[cur][dd][tx * 8])[0];
            ulonglong2 m1 = ((const ulonglong2*)&sM[cur][dd][tx * 8])[1];
            unsigned long long mm[4] = { m0.x, m0.y, m1.x, m1.y };
            unsigned long long xx[8] = { pk2(xa.x), pk2(xa.y), pk2(xa.z), pk2(xa.w),
                                         pk2(xb.x), pk2(xb.y), pk2(xb.z), pk2(xb.w) };
            #pragma unroll
            for (int i = 0; i < 8; i++)
                #pragma unroll
                for (int j = 0; j < 4; j++) fma2(acc[i][j], xx[i], mm[j]);
        }
        if (dc < 11) {
            sX[nxt][q * 4 + 0][cA] = pxA.x; sX[nxt][q * 4 + 1][cA] = pxA.y;
            sX[nxt][q * 4 + 2][cA] = pxA.z; sX[nxt][q * 4 + 3][cA] = pxA.w;
            sX[nxt][q * 4 + 0][cB] = pxB.x; sX[nxt][q * 4 + 1][cB] = pxB.y;
            sX[nxt][q * 4 + 2][cB] = pxB.z; sX[nxt][q * 4 + 3][cB] = pxB.w;
        }
    }
    __syncthreads();
    if (tid < 128) sScale[tid] = SCALE_L / sqrtf(fmaxf(nacc, 1e-12f));
    __syncthreads();

    float ep[8];
    #pragma unroll
    for (int c = 0; c < 8; c++) ep[c] = 0.f;
    #pragma unroll
    for (int i = 0; i < 8; i++) {
        int tok = ty * 8 + i;
        float sc = sScale[tok];
        float o[8];
        #pragma unroll
        for (int j = 0; j < 4; j++) {
            float2 p = up2(acc[i][j]);
            o[2 * j]     = p.x * sc;
            o[2 * j + 1] = p.y * sc;
        }
        float4* dst = (float4*)(g_Lc + (size_t)(t0 + tok) * K_CODE + tx * 8);
        dst[0] = make_float4(o[0], o[1], o[2], o[3]);
        dst[1] = make_float4(o[4], o[5], o[6], o[7]);
        #pragma unroll
        for (int c = 0; c < 8; c++) ep[c] += ex2f(o[c]);
    }
    #pragma unroll
    for (int c = 0; c < 8; c++) sRed[ty][tx * 8 + c] = ep[c];
    __syncthreads();
    if (tid < 128) {
        float s = 0.f;
        #pragma unroll
        for (int r = 0; r < 16; r++) s += sRed[r][tid];   // tokens 0..127 ascending
        g_Rpart[blockIdx.x * K_CODE + tid] = s;
    }
    // fused r1 reduce: last block to finish performs the old kreduce(0)
    if (last_block(0, tid, GBLK)) tail_reduce(0, tid);
}

// ---------------- Sinkhorn pass (R14 body) + fused reduce tail --------------
__global__ void kpass(int mode) {   // grid 1024, block 256
    int lane = threadIdx.x & 31, w = threadIdx.x >> 5;
    int tok0 = (blockIdx.x * 8 + w) * 16;
    float r0 = g_rvec[lane * 4 + 0], r1 = g_rvec[lane * 4 + 1];
    float r2 = g_rvec[lane * 4 + 2], r3 = g_rvec[lane * 4 + 3];
    float a0 = 0.f, a1 = 0.f, a2 = 0.f, a3 = 0.f;
    #pragma unroll
    for (int g = 0; g < 2; g++) {
        float e[8][4], t[8];
        #pragma unroll
        for (int j = 0; j < 8; j++) {
            float4 lc = *(const float4*)(g_Lc + (size_t)(tok0 + g * 8 + j) * K_CODE + lane * 4);
            e[j][0] = ex2f(lc.x); e[j][1] = ex2f(lc.y);
            e[j][2] = ex2f(lc.z); e[j][3] = ex2f(lc.w);
            t[j] = fmaf(e[j][0], r0, fmaf(e[j][1], r1, fmaf(e[j][2], r2, e[j][3] * r3)));
        }
        #pragma unroll
        for (int off = 16; off > 0; off >>= 1) {
            #pragma unroll
            for (int j = 0; j < 8; j++)
                t[j] += __shfl_xor_sync(0xffffffffu, t[j], off);
        }
        #pragma unroll
        for (int j = 0; j < 8; j++) {      // ascending token order (bit order kept)
            float c = 1.0f / t[j];
            a0 = fmaf(e[j][0], c, a0); a1 = fmaf(e[j][1], c, a1);
            a2 = fmaf(e[j][2], c, a2); a3 = fmaf(e[j][3], c, a3);
        }
    }
    __shared__ float sm[8][K_CODE];
    sm[w][lane * 4 + 0] = a0; sm[w][lane * 4 + 1] = a1;
    sm[w][lane * 4 + 2] = a2; sm[w][lane * 4 + 3] = a3;
    __syncthreads();
    int t = threadIdx.x;
    if (t < K_CODE) {
        float s = 0.f;
        #pragma unroll
        for (int ww = 0; ww < 8; ww++) s += sm[ww][t];
        g_Rpart[blockIdx.x * K_CODE + t] = s;
    }
    // fused reduce: mode 0 -> r2 (counter 1), mode 1 -> lr3 (counter 2)
    if (last_block(1 + mode, t, GBLK)) tail_reduce(mode, t);
}

// ---------------- argmax + gather + GLU output — streaming everywhere -------
__global__ void kfinal(const float* __restrict__ proj, float* __restrict__ out) {
    int lane = threadIdx.x & 31, w = threadIdx.x >> 5;
    int tok0 = (blockIdx.x * 8 + w) * 16;
    float l0 = g_lr3[lane * 4 + 0], l1 = g_lr3[lane * 4 + 1];
    float l2 = g_lr3[lane * 4 + 2], l3 = g_lr3[lane * 4 + 3];
    for (int g = 0; g < 4; g++) {
        float lbv[4], bv[4];
        int lbk[4], bk[4];
        #pragma unroll
        for (int j = 0; j < 4; j++) {
            int n = tok0 + g * 4 + j;
            float4 lc = ldcs4(g_Lc + (size_t)n * K_CODE + lane * 4);  // last reader
            float v0 = lc.x + l0, v1 = lc.y + l1, v2 = lc.z + l2, v3 = lc.w + l3;
            float b_ = v0; int k_ = lane * 4;
            if (v1 > b_) { b_ = v1; k_ = lane * 4 + 1; }
            if (v2 > b_) { b_ = v2; k_ = lane * 4 + 2; }
            if (v3 > b_) { b_ = v3; k_ = lane * 4 + 3; }
            lbv[j] = b_; lbk[j] = k_; bv[j] = b_;
        }
        #pragma unroll
        for (int off = 16; off > 0; off >>= 1) {
            bv[0] = fmaxf(bv[0], __shfl_xor_sync(0xffffffffu, bv[0], off));
            bv[1] = fmaxf(bv[1], __shfl_xor_sync(0xffffffffu, bv[1], off));
            bv[2] = fmaxf(bv[2], __shfl_xor_sync(0xffffffffu, bv[2], off));
            bv[3] = fmaxf(bv[3], __shfl_xor_sync(0xffffffffu, bv[3], off));
        }
        #pragma unroll
        for (int j = 0; j < 4; j++) {
            unsigned mask = __ballot_sync(0xffffffffu, lbv[j] == bv[j]);
            int src = __ffs(mask) - 1;
            bk[j] = __shfl_sync(0xffffffffu, lbk[j], src);
        }
        #pragma unroll
        for (int j = 0; j < 4; j++) {
            int n = tok0 + g * 4 + j;
            const float4* hp = (const float4*)(g_hg + bk[j] * D_DIM);
            const float*  pp = proj + (size_t)n * D_DIM;
            float*        op = out  + (size_t)n * D_DIM;
            float4 p1 = ldcs4(pp + lane * 4), h1 = hp[lane];
            float4 o1;
            o1.x = fmaf(0.5f, p1.x, h1.x); o1.y = fmaf(0.5f, p1.y, h1.y);
            o1.z = fmaf(0.5f, p1.z, h1.z); o1.w = fmaf(0.5f, p1.w, h1.w);
            stcs4(op + lane * 4, o1);
            if (lane < 16) {
                float4 p2 = ldcs4(pp + 128 + lane * 4), h2 = hp[32 + lane];
                float4 o2;
                o2.x = fmaf(0.5f, p2.x, h2.x); o2.y = fmaf(0.5f, p2.y, h2.y);
                o2.z = fmaf(0.5f, p2.z, h2.z); o2.w = fmaf(0.5f, p2.w, h2.w);
                stcs4(op + 128 + lane * 4, o2);
            }
        }
    }
}

// ---------------- launch -----------------------------------------------------
extern "C" void kernel_launch(void* const* d_in, const int* in_sizes, int n_in,
                              void* d_out, int out_size) {
    const float* proj = (const float*)d_in[0];
    const float* mem  = (const float*)d_in[1];
    const float* W    = (const float*)d_in[2];
    const float* b    = (const float*)d_in[3];
    float* out = (float*)d_out;

    kprep<<<K_CODE, D_DIM>>>(mem, W, b);   // also resets counters
    kgemm<<<GBLK, 256>>>(proj);            // + fused r1 reduce
    kpass<<<GBLK, 256>>>(0);               // c1 pass + fused r2 reduce
    kpass<<<GBLK, 256>>>(1);               // c2 pass + fused lr3 reduce
    kfinal<<<GBLK, 256>>>(proj, out);
}

// round 17
// speedup vs baseline: 1.1191x; 1.1191x over previous
#include <cuda_runtime.h>
#include <math.h>
#include <stdint.h>

#define N_TOK   131072
#define D_DIM   192
#define K_CODE  128
#define GBLK    1024              // N_TOK / 128
#define SCALE_L 28.853900817779268f   // 20 / ln(2): Lc = cos*20*log2(e)

// ---------------- scratch (device globals; no runtime allocation) ------------
__device__ float g_Lc[(size_t)N_TOK * K_CODE];   // 67 MB: Lc[n][k]
__device__ float g_Rpart[GBLK * K_CODE];         // block partials, [block][k]
__device__ float g_rvec[K_CODE];                 // r1 then r2
__device__ float g_lr3[K_CODE];                  // log2(r3)
__device__ __align__(16) float g_memT[D_DIM * K_CODE];  // normalized bank, [d][k]
__device__ __align__(16) float g_hg[K_CODE * D_DIM];    // 0.5 * gated(mem_bank[k])

// ---------------- small helpers ---------------------------------------------
__device__ __forceinline__ float ex2f(float x) {
    float y; asm("ex2.approx.f32 %0, %1;" : "=f"(y) : "f"(x)); return y;
}
__device__ __forceinline__ unsigned long long pk2(float x) {
    unsigned long long r; asm("mov.b64 %0, {%1, %1};" : "=l"(r) : "f"(x)); return r;
}
__device__ __forceinline__ float2 up2(unsigned long long v) {
    float2 r; asm("mov.b64 {%0, %1}, %2;" : "=f"(r.x), "=f"(r.y) : "l"(v)); return r;
}
__device__ __forceinline__ void fma2(unsigned long long& a, unsigned long long x,
                                     unsigned long long m) {
    asm("fma.rn.f32x2 %0, %1, %2, %0;" : "+l"(a) : "l"(x), "l"(m));
}
__device__ __forceinline__ void cpa16(uint32_t dst, const void* src) {
    asm volatile("cp.async.cg.shared.global [%0], [%1], 16;" :: "r"(dst), "l"(src));
}
__device__ __forceinline__ void cpa_commit() {
    asm volatile("cp.async.commit_group;");
}
__device__ __forceinline__ void cpa_wait0() {
    asm volatile("cp.async.wait_group 0;");
}
// streaming (evict-first) float4 load / store
__device__ __forceinline__ float4 ldcs4(const float* p) {
    float4 v;
    asm volatile("ld.global.cs.v4.f32 {%0,%1,%2,%3}, [%4];"
                 : "=f"(v.x), "=f"(v.y), "=f"(v.z), "=f"(v.w) : "l"(p));
    return v;
}
__device__ __forceinline__ void stcs4(float* p, float4 v) {
    asm volatile("st.global.cs.v4.f32 [%0], {%1,%2,%3,%4};"
                 :: "l"(p), "f"(v.x), "f"(v.y), "f"(v.z), "f"(v.w));
}
// 16B-granular XOR swizzle along the token axis of an sX row (col in floats)
__device__ __forceinline__ int swzc(int c) { return c ^ (((c >> 5) & 1) << 2); }

// ---------------- K0: per-code norm + transposed bank + GLU table (fused) ---
__global__ void kprep(const float* __restrict__ mem, const float* __restrict__ W,
                      const float* __restrict__ b) {
    __shared__ float a[D_DIM];
    __shared__ float s_scale;
    int k = blockIdx.x, j = threadIdx.x;
    a[j] = mem[k * D_DIM + j];
    __syncthreads();
    if (j == 0) {
        float s = 0.f;
        #pragma unroll 8
        for (int d = 0; d < D_DIM; d++) s = fmaf(a[d], a[d], s);   // R2 bit order
        s_scale = 1.0f / sqrtf(fmaxf(s, 1e-12f));
    }
    __syncthreads();
    g_memT[j * K_CODE + k] = a[j] * s_scale;
    float av = b[j], ag = b[j + D_DIM];
    #pragma unroll 4
    for (int d = 0; d < D_DIM; d++) {
        float xd = a[d];
        av = fmaf(xd, W[d * 2 * D_DIM + j], av);
        ag = fmaf(xd, W[d * 2 * D_DIM + D_DIM + j], ag);
    }
    float sig = 1.0f / (1.0f + expf(-ag));
    g_hg[k * D_DIM + j] = 0.5f * av * sig;
}

// ---------------- K1: similarity GEMM — R10 known-good + streaming proj -----
__global__ __launch_bounds__(256, 2) void kgemm(const float* __restrict__ proj) {
    __shared__ __align__(16) float sX[2][16][132];   // [buf][dd][token(swz)+pad]
    __shared__ __align__(16) float sM[2][16][128];   // [buf][dd][code]
    __shared__ float sScale[128];
    __shared__ float sRed[16][128];

    int tid = threadIdx.x, lane = tid & 31, w = tid >> 5;
    int tx = (lane & 3) | ((w & 3) << 2);         // code group (4 distinct / warp)
    int ty = ((lane >> 2) & 7) | ((w >> 2) << 3); // token group (8 distinct / warp)
    int t0 = blockIdx.x << 7;
    int tokA = tid >> 2, q = tid & 3, tokB = tokA + 64;
    int cA = swzc(tokA), cB = swzc(tokB);

    uint32_t mb0 = (uint32_t)__cvta_generic_to_shared(&sM[0][0][0]);
    uint32_t mb1 = (uint32_t)__cvta_generic_to_shared(&sM[1][0][0]);
    int fA = tid, fB = tid + 256;

    unsigned long long acc[8][4];
    #pragma unroll
    for (int i = 0; i < 8; i++)
        #pragma unroll
        for (int j = 0; j < 4; j++) acc[i][j] = 0ULL;
    float nacc = 0.f;

    auto stageM = [&](int dc, int buf) {
        uint32_t mb = buf ? mb1 : mb0;
        cpa16(mb + (uint32_t)(fA * 16), g_memT + dc * 2048 + fA * 4);
        cpa16(mb + (uint32_t)(fB * 16), g_memT + dc * 2048 + fB * 4);
        cpa_commit();
    };

    stageM(0, 0);
    {
        float4 xA = ldcs4(proj + (size_t)(t0 + tokA) * D_DIM + q * 4);
        float4 xB = ldcs4(proj + (size_t)(t0 + tokB) * D_DIM + q * 4);
        sX[0][q * 4 + 0][cA] = xA.x; sX[0][q * 4 + 1][cA] = xA.y;
        sX[0][q * 4 + 2][cA] = xA.z; sX[0][q * 4 + 3][cA] = xA.w;
        sX[0][q * 4 + 0][cB] = xB.x; sX[0][q * 4 + 1][cB] = xB.y;
        sX[0][q * 4 + 2][cB] = xB.z; sX[0][q * 4 + 3][cB] = xB.w;
    }

    for (int dc = 0; dc < 12; dc++) {
        int cur = dc & 1, nxt = cur ^ 1;
        cpa_wait0();
        __syncthreads();

        float4 pxA, pxB;
        if (dc < 11) {
            stageM(dc + 1, nxt);
            pxA = ldcs4(proj + (size_t)(t0 + tokA) * D_DIM + (dc + 1) * 16 + q * 4);
            pxB = ldcs4(proj + (size_t)(t0 + tokB) * D_DIM + (dc + 1) * 16 + q * 4);
        }

        if (tid < 128) {
            int ct = swzc(tid);
            #pragma unroll
            for (int dd = 0; dd < 16; dd++) {
                float x = sX[cur][dd][ct];
                nacc = fmaf(x, x, nacc);
            }
        }
        #pragma unroll
        for (int dd = 0; dd < 16; dd++) {
            float4 xa = *(const float4*)&sX[cur][dd][swzc(ty * 8)];
            float4 xb = *(const float4*)&sX[cur][dd][swzc(ty * 8 + 4)];
            ulonglong2 m0 = ((const ulonglong2*)&sM[cur][dd][tx * 8])[0];
            ulonglong2 m1 = ((const ulonglong2*)&sM[cur][dd][tx * 8])[1];
            unsigned long long mm[4] = { m0.x, m0.y, m1.x, m1.y };
            unsigned long long xx[8] = { pk2(xa.x), pk2(xa.y), pk2(xa.z), pk2(xa.w),
                                         pk2(xb.x), pk2(xb.y), pk2(xb.z), pk2(xb.w) };
            #pragma unroll
            for (int i = 0; i < 8; i++)
                #pragma unroll
                for (int j = 0; j < 4; j++) fma2(acc[i][j], xx[i], mm[j]);
        }
        if (dc < 11) {
            sX[nxt][q * 4 + 0][cA] = pxA.x; sX[nxt][q * 4 + 1][cA] = pxA.y;
            sX[nxt][q * 4 + 2][cA] = pxA.z; sX[nxt][q * 4 + 3][cA] = pxA.w;
            sX[nxt][q * 4 + 0][cB] = pxB.x; sX[nxt][q * 4 + 1][cB] = pxB.y;
            sX[nxt][q * 4 + 2][cB] = pxB.z; sX[nxt][q * 4 + 3][cB] = pxB.w;
        }
    }
    __syncthreads();
    if (tid < 128) sScale[tid] = SCALE_L / sqrtf(fmaxf(nacc, 1e-12f));
    __syncthreads();

    float ep[8];
    #pragma unroll
    for (int c = 0; c < 8; c++) ep[c] = 0.f;
    #pragma unroll
    for (int i = 0; i < 8; i++) {
        int tok = ty * 8 + i;
        float sc = sScale[tok];
        float o[8];
        #pragma unroll
        for (int j = 0; j < 4; j++) {
            float2 p = up2(acc[i][j]);
            o[2 * j]     = p.x * sc;
            o[2 * j + 1] = p.y * sc;
        }
        float4* dst = (float4*)(g_Lc + (size_t)(t0 + tok) * K_CODE + tx * 8);
        dst[0] = make_float4(o[0], o[1], o[2], o[3]);
        dst[1] = make_float4(o[4], o[5], o[6], o[7]);
        #pragma unroll
        for (int c = 0; c < 8; c++) ep[c] += ex2f(o[c]);
    }
    #pragma unroll
    for (int c = 0; c < 8; c++) sRed[ty][tx * 8 + c] = ep[c];
    __syncthreads();
    if (tid < 128) {
        float s = 0.f;
        #pragma unroll
        for (int r = 0; r < 16; r++) s += sRed[r][tid];   // tokens 0..127 ascending
        g_Rpart[blockIdx.x * K_CODE + tid] = s;
    }
}

// ---------------- reduction: same bit order, MLP 32 -------------------------
__global__ void kreduce(int mode) {   // grid 128, block 32
    __shared__ float sm[4];
    int k = blockIdx.x, lane = threadIdx.x;
    if (lane < 4) {
        float s = 0.f;
        const float* p = g_Rpart + (size_t)(lane * 256) * K_CODE + k;
        #pragma unroll 32
        for (int i = 0; i < 256; i++) s += p[(size_t)i * K_CODE];
        sm[lane] = s;
    }
    __syncthreads();
    if (lane == 0) {
        float tot = ((sm[0] + sm[1]) + sm[2]) + sm[3];
        if (mode == 0) g_rvec[k] = 1.0f / tot;
        else           g_lr3[k]  = -log2f(tot);
    }
}

// ---------------- Sinkhorn pass, 8-token batched (R14 body) -----------------
__global__ void kpass() {   // grid 1024, block 256
    int lane = threadIdx.x & 31, w = threadIdx.x >> 5;
    int tok0 = (blockIdx.x * 8 + w) * 16;
    float r0 = g_rvec[lane * 4 + 0], r1 = g_rvec[lane * 4 + 1];
    float r2 = g_rvec[lane * 4 + 2], r3 = g_rvec[lane * 4 + 3];
    float a0 = 0.f, a1 = 0.f, a2 = 0.f, a3 = 0.f;
    #pragma unroll
    for (int g = 0; g < 2; g++) {
        float e[8][4], t[8];
        #pragma unroll
        for (int j = 0; j < 8; j++) {
            float4 lc = *(const float4*)(g_Lc + (size_t)(tok0 + g * 8 + j) * K_CODE + lane * 4);
            e[j][0] = ex2f(lc.x); e[j][1] = ex2f(lc.y);
            e[j][2] = ex2f(lc.z); e[j][3] = ex2f(lc.w);
            t[j] = fmaf(e[j][0], r0, fmaf(e[j][1], r1, fmaf(e[j][2], r2, e[j][3] * r3)));
        }
        #pragma unroll
        for (int off = 16; off > 0; off >>= 1) {
            #pragma unroll
            for (int j = 0; j < 8; j++)
                t[j] += __shfl_xor_sync(0xffffffffu, t[j], off);
        }
        #pragma unroll
        for (int j = 0; j < 8; j++) {      // ascending token order (bit order kept)
            float c = 1.0f / t[j];
            a0 = fmaf(e[j][0], c, a0); a1 = fmaf(e[j][1], c, a1);
            a2 = fmaf(e[j][2], c, a2); a3 = fmaf(e[j][3], c, a3);
        }
    }
    __shared__ float sm[8][K_CODE];
    sm[w][lane * 4 + 0] = a0; sm[w][lane * 4 + 1] = a1;
    sm[w][lane * 4 + 2] = a2; sm[w][lane * 4 + 3] = a3;
    __syncthreads();
    int t = threadIdx.x;
    if (t < K_CODE) {
        float s = 0.f;
        #pragma unroll
        for (int ww = 0; ww < 8; ww++) s += sm[ww][t];
        g_Rpart[blockIdx.x * K_CODE + t] = s;
    }
}

// ---------------- argmax + gather + GLU output — streaming everywhere -------
__global__ void kfinal(const float* __restrict__ proj, float* __restrict__ out) {
    int lane = threadIdx.x & 31, w = threadIdx.x >> 5;
    int tok0 = (blockIdx.x * 8 + w) * 16;
    float l0 = g_lr3[lane * 4 + 0], l1 = g_lr3[lane * 4 + 1];
    float l2 = g_lr3[lane * 4 + 2], l3 = g_lr3[lane * 4 + 3];
    for (int g = 0; g < 4; g++) {
        float lbv[4], bv[4];
        int lbk[4], bk[4];
        #pragma unroll
        for (int j = 0; j < 4; j++) {
            int n = tok0 + g * 4 + j;
            float4 lc = ldcs4(g_Lc + (size_t)n * K_CODE + lane * 4);  // last reader
            float v0 = lc.x + l0, v1 = lc.y + l1, v2 = lc.z + l2, v3 = lc.w + l3;
            float b_ = v0; int k_ = lane * 4;
            if (v1 > b_) { b_ = v1; k_ = lane * 4 + 1; }
            if (v2 > b_) { b_ = v2; k_ = lane * 4 + 2; }
            if (v3 > b_) { b_ = v3; k_ = lane * 4 + 3; }
            lbv[j] = b_; lbk[j] = k_; bv[j] = b_;
        }
        #pragma unroll
        for (int off = 16; off > 0; off >>= 1) {
            bv[0] = fmaxf(bv[0], __shfl_xor_sync(0xffffffffu, bv[0], off));
            bv[1] = fmaxf(bv[1], __shfl_xor_sync(0xffffffffu, bv[1], off));
            bv[2] = fmaxf(bv[2], __shfl_xor_sync(0xffffffffu, bv[2], off));
            bv[3] = fmaxf(bv[3], __shfl_xor_sync(0xffffffffu, bv[3], off));
        }
        #pragma unroll
        for (int j = 0; j < 4; j++) {
            unsigned mask = __ballot_sync(0xffffffffu, lbv[j] == bv[j]);
            int src = __ffs(mask) - 1;
            bk[j] = __shfl_sync(0xffffffffu, lbk[j], src);
        }
        #pragma unroll
        for (int j = 0; j < 4; j++) {
            int n = tok0 + g * 4 + j;
            const float4* hp = (const float4*)(g_hg + bk[j] * D_DIM);
            const float*  pp = proj + (size_t)n * D_DIM;
            float*        op = out  + (size_t)n * D_DIM;
            float4 p1 = ldcs4(pp + lane * 4), h1 = hp[lane];
            float4 o1;
            o1.x = fmaf(0.5f, p1.x, h1.x); o1.y = fmaf(0.5f, p1.y, h1.y);
            o1.z = fmaf(0.5f, p1.z, h1.z); o1.w = fmaf(0.5f, p1.w, h1.w);
            stcs4(op + lane * 4, o1);
            if (lane < 16) {
                float4 p2 = ldcs4(pp + 128 + lane * 4), h2 = hp[32 + lane];
                float4 o2;
                o2.x = fmaf(0.5f, p2.x, h2.x); o2.y = fmaf(0.5f, p2.y, h2.y);
                o2.z = fmaf(0.5f, p2.z, h2.z); o2.w = fmaf(0.5f, p2.w, h2.w);
                stcs4(op + 128 + lane * 4, o2);
            }
        }
    }
}

// ---------------- launch -----------------------------------------------------
extern "C" void kernel_launch(void* const* d_in, const int* in_sizes, int n_in,
                              void* d_out, int out_size) {
    const float* proj = (const float*)d_in[0];
    const float* mem  = (const float*)d_in[1];
    const float* W    = (const float*)d_in[2];
    const float* b    = (const float*)d_in[3];
    float* out = (float*)d_out;

    kprep<<<K_CODE, D_DIM>>>(mem, W, b);
    kgemm<<<GBLK, 256>>>(proj);
    kreduce<<<K_CODE, 32>>>(0);    // r1
    kpass<<<GBLK, 256>>>();        // c1, partials for r2
    kreduce<<<K_CODE, 32>>>(0);    // r2
    kpass<<<GBLK, 256>>>();        // c2, partials for r3
    kreduce<<<K_CODE, 32>>>(1);    // log2(r3)
    kfinal<<<GBLK, 256>>>(proj, out);
}